// round 6
// baseline (speedup 1.0000x reference)
#include <cuda_runtime.h>
#include <cuda_bf16.h>
#include <cstdint>
#include <cfloat>

// GaussianLayer: out[m,k] = tanh(scale[k]) * exp(-zz - mm + 2*zm)
//   d[k,i]  = 0.1 + 0.9*sigmoid(diag[k,i]),  d in (0.1, 1.0)
//   exponent = -sum_i d[k,i]*(z[m,i]-mean[k,i])^2  <= 0 (exact identity)
// Weighted Cauchy-Schwarz (with d <= 1):
//   sum_i d*(z-mean)^2 >= (sqrt(mm[k]) - ||z_m||)^2  when sqrt(mm[k]) >= ||z_m||
// If sqrt(mm[k]) > ||z_m|| + 12, exponent < -144 < -104 => expf underflows
// to exactly +-0.0f, so the element is exactly 0.0f. Elements failing the
// bound use the exact fp32 reference expression.
//
// Structure (2 kernels, no global reductions, no flag):
//   K1: per-out-feature sqrt(sum d*mean^2) and tanh(scale)   (16 MB read)
//   K2: FUSED: each block owns 4 m-rows; computes their z-norms in-block
//       (16 KB read), then streams 32 KB of bound-tested stores. z-read and
//       out-write overlap on HBM instead of serializing as two waves.

#define MAX_OUT 2048

__device__ float g_sq[MAX_OUT];  // sqrt(sum_i d*mean^2)
__device__ float g_ts[MAX_OUT];  // tanh(scale)

// ================= Kernel 1: k-stats ======================================
// One warp per out-feature. Fast sigmoid feeds only the conservative bound
// (margin >> approx error); the exact fallback never uses these values.
__global__ void __launch_bounds__(256) kstats_kernel(
    const float* __restrict__ diag, const float* __restrict__ mean,
    const float* __restrict__ scale, int out_f, int in_f)
{
    int k = blockIdx.x * 8 + (threadIdx.x >> 5);
    int lane = threadIdx.x & 31;
    if (k >= out_f) return;
    int n4 = in_f >> 2;
    const float4* dr = reinterpret_cast<const float4*>(diag + (size_t)k * in_f);
    const float4* mr = reinterpret_cast<const float4*>(mean + (size_t)k * in_f);
    float s = 0.0f;
    #pragma unroll 4
    for (int i = lane; i < n4; i += 32) {
        float4 dv = __ldcs(&dr[i]);
        float4 mv = __ldcs(&mr[i]);
        float d0 = 0.1f + __fdividef(0.9f, 1.0f + __expf(-dv.x));
        float d1 = 0.1f + __fdividef(0.9f, 1.0f + __expf(-dv.y));
        float d2 = 0.1f + __fdividef(0.9f, 1.0f + __expf(-dv.z));
        float d3 = 0.1f + __fdividef(0.9f, 1.0f + __expf(-dv.w));
        s += d0 * mv.x * mv.x + d1 * mv.y * mv.y
           + d2 * mv.z * mv.z + d3 * mv.w * mv.w;
    }
    #pragma unroll
    for (int o = 16; o; o >>= 1) s += __shfl_xor_sync(0xFFFFFFFFu, s, o);
    if (lane == 0) {
        g_sq[k] = sqrtf(s);
        g_ts[k] = tanhf(scale[k]);
    }
}

// ================= Fallback: exact fp32 reference expression ==============
__device__ __noinline__ float slow_elem(
    const float* __restrict__ z, const float* __restrict__ diag,
    const float* __restrict__ mean, int mrow, int k, int in_f)
{
    const float* zr = z + (size_t)mrow * in_f;
    const float* dr = diag + (size_t)k * in_f;
    const float* mr = mean + (size_t)k * in_f;
    float zz = 0.0f, zm = 0.0f, mm = 0.0f;
    for (int i = 0; i < in_f; i++) {
        float d = 0.1f + 0.9f / (1.0f + expf(-dr[i]));
        float zi = zr[i];
        float mi = mr[i];
        zz += d * zi * zi;
        zm += zi * d * mi;
        mm += d * mi * mi;
    }
    return g_ts[k] * expf(-zz - mm + 2.0f * zm);
}

// ================= Kernel 2: fused norm + output ==========================
// Block = 256 threads, owns ROWS=4 m-rows. Phase 1: compute ||z_row|| for
// the 4 rows (each thread contributes one strided float4 per row -> MLP=4).
// Phase 2: stream 4*n4row float4 stores; per float4, test min(g_sq[k..k+3])
// (L1-resident 8 KB table) against the row threshold.
#define ROWS 4

__global__ void __launch_bounds__(256) fused_kernel(
    const float* __restrict__ z, const float* __restrict__ diag,
    const float* __restrict__ mean, float* __restrict__ out,
    int m, int out_f, int in_f, int n4row, int row_shift)
{
    __shared__ float s_part[ROWS][8];
    __shared__ float s_thr[ROWS];

    int tid = threadIdx.x;
    int lane = tid & 31;
    int wid = tid >> 5;
    int row0 = blockIdx.x * ROWS;
    int n4in = in_f >> 2;
    const float4* z4 = reinterpret_cast<const float4*>(z);

    // ---- Phase 1: z-row norms ----
    float s[ROWS];
    #pragma unroll
    for (int j = 0; j < ROWS; j++) s[j] = 0.0f;

    #pragma unroll
    for (int j = 0; j < ROWS; j++) {
        int row = row0 + j;
        if (row >= m) break;
        const float4* rp = &z4[(size_t)row * n4in];
        for (int i = tid; i < n4in; i += 256) {
            float4 v = __ldcs(&rp[i]);
            s[j] += v.x * v.x + v.y * v.y + v.z * v.z + v.w * v.w;
        }
    }
    #pragma unroll
    for (int j = 0; j < ROWS; j++) {
        #pragma unroll
        for (int o = 16; o; o >>= 1)
            s[j] += __shfl_xor_sync(0xFFFFFFFFu, s[j], o);
        if (lane == 0) s_part[j][wid] = s[j];
    }
    __syncthreads();
    if (tid < ROWS) {
        float t = 0.0f;
        #pragma unroll
        for (int w = 0; w < 8; w++) t += s_part[tid][w];
        s_thr[tid] = sqrtf(t) + 12.0f;
    }
    __syncthreads();

    // ---- Phase 2: bound-tested streaming stores ----
    const float4* sq4 = reinterpret_cast<const float4*>(g_sq);
    float4* out4 = reinterpret_cast<float4*>(out);
    const float4 zero4 = make_float4(0.0f, 0.0f, 0.0f, 0.0f);
    int total4 = ROWS * n4row;
    size_t base4 = (size_t)row0 * n4row;

    #pragma unroll 8
    for (int u = tid; u < total4; u += 256) {
        int j = (row_shift >= 0) ? (u >> row_shift)
                                 : (int)((unsigned)u / (unsigned)n4row);
        int row = row0 + j;
        if (row >= m) break;
        int k4 = u - j * n4row;
        float thr = s_thr[j];
        float4 q = sq4[k4];                       // L1-resident (8 KB table)
        float qmin = fminf(fminf(q.x, q.y), fminf(q.z, q.w));
        if (qmin > thr) {
            __stcs(&out4[base4 + u], zero4);
        } else {
            int kbase = k4 * 4;
            float4 r4;
            r4.x = (q.x > thr) ? 0.0f : slow_elem(z, diag, mean, row, kbase + 0, in_f);
            r4.y = (q.y > thr) ? 0.0f : slow_elem(z, diag, mean, row, kbase + 1, in_f);
            r4.z = (q.z > thr) ? 0.0f : slow_elem(z, diag, mean, row, kbase + 2, in_f);
            r4.w = (q.w > thr) ? 0.0f : slow_elem(z, diag, mean, row, kbase + 3, in_f);
            out4[base4 + u] = r4;
        }
    }
}

extern "C" void kernel_launch(void* const* d_in, const int* in_sizes, int n_in,
                              void* d_out, int out_size)
{
    const float* z     = (const float*)d_in[0];  // (m, in_f)
    const float* diag  = (const float*)d_in[1];  // (out_f, in_f)
    const float* mean  = (const float*)d_in[2];  // (out_f, in_f, 1)
    const float* scale = (const float*)d_in[3];  // (out_f,)
    float* out = (float*)d_out;

    int out_f = in_sizes[3];
    int in_f  = in_sizes[1] / out_f;
    int m     = in_sizes[0] / in_f;

    // Kernel 1: k-stats (one warp per out-feature)
    int nb_k = (out_f + 7) / 8;
    kstats_kernel<<<nb_k, 256>>>(diag, mean, scale, out_f, in_f);

    // Kernel 2: fused z-norm + output, 4 rows per 256-thread block
    int n4row = out_f >> 2;
    int row_shift = -1;
    if ((n4row & (n4row - 1)) == 0) {
        row_shift = 0;
        while ((1 << row_shift) != n4row) row_shift++;
    }
    int nb = (m + ROWS - 1) / ROWS;
    fused_kernel<<<nb, 256>>>(z, diag, mean, out, m, out_f, in_f,
                              n4row, row_shift);
}

// round 7
// speedup vs baseline: 1.2417x; 1.2417x over previous
#include <cuda_runtime.h>
#include <cuda_bf16.h>
#include <cstdint>
#include <cfloat>

// GaussianLayer: out[m,k] = tanh(scale[k]) * exp(-zz - mm + 2*zm)
//   d[k,i]  = 0.1 + 0.9*sigmoid(diag[k,i]),  d in (0.1, 1.0)
//   exponent = -sum_i d[k,i]*(z[m,i]-mean[k,i])^2  <= 0 (exact identity)
// Weighted Cauchy-Schwarz (with d <= 1):
//   sum_i d*(z-mean)^2 >= (sqrt(mm[k]) - ||z_m||)^2  when sqrt(mm[k]) >= ||z_m||
// If sqrt(mm[k]) > ||z_m|| + 12, exponent < -144 < -104 => expf underflows
// to exactly +-0.0f, so the element is exactly 0.0f. Elements failing the
// bound use the exact fp32 reference expression.
//
// Structure: exactly TWO graph nodes (each extra node costs ~3-4 us):
//   K1 prep: row norms ||z_m|| (one warp/row, 8 loads in flight) and
//            k-stats sqrt(sum d*mean^2), tanh(scale)   [80 MB read]
//   K2 out:  flat streaming store; per float4 the bound test reads only the
//            L1-resident g_sq table (8 KB) and g_zn[row].  [128 MB write]

#define MAX_M 16384
#define MAX_OUT 2048

__device__ float g_zn[MAX_M];    // ||z_m||
__device__ float g_sq[MAX_OUT];  // sqrt(sum_i d*mean^2)
__device__ float g_ts[MAX_OUT];  // tanh(scale)

// ================= Kernel 1: prep (row norms + k-stats) ==================
// 512 threads = 16 warps per block; one warp per m-row / out-feature.
__global__ void __launch_bounds__(512) prep_kernel(
    const float* __restrict__ z,
    const float* __restrict__ diag, const float* __restrict__ mean,
    const float* __restrict__ scale,
    int m, int out_f, int in_f, int nb_m)
{
    int wid_in_blk = threadIdx.x >> 5;
    int lane = threadIdx.x & 31;
    int n4 = in_f >> 2;

    if (blockIdx.x < nb_m) {
        // ---- row norm of z: 8 independent float4 loads per lane ----
        int row = blockIdx.x * 16 + wid_in_blk;
        if (row >= m) return;
        const float4* rp = reinterpret_cast<const float4*>(z + (size_t)row * in_f);
        float s = 0.0f;
        if (n4 == 256) {
            float4 v[8];
            #pragma unroll
            for (int j = 0; j < 8; j++) v[j] = __ldcs(&rp[lane + 32 * j]);
            #pragma unroll
            for (int j = 0; j < 8; j++)
                s += v[j].x * v[j].x + v[j].y * v[j].y
                   + v[j].z * v[j].z + v[j].w * v[j].w;
        } else {
            for (int i = lane; i < n4; i += 32) {
                float4 v = __ldcs(&rp[i]);
                s += v.x * v.x + v.y * v.y + v.z * v.z + v.w * v.w;
            }
        }
        #pragma unroll
        for (int o = 16; o; o >>= 1) s += __shfl_xor_sync(0xFFFFFFFFu, s, o);
        if (lane == 0) g_zn[row] = sqrtf(s);
    } else {
        // ---- k-stats. Fast sigmoid feeds only the conservative bound
        // (margin >> approx error); the exact fallback never uses it.
        int k = (blockIdx.x - nb_m) * 16 + wid_in_blk;
        if (k >= out_f) return;
        const float4* dr = reinterpret_cast<const float4*>(diag + (size_t)k * in_f);
        const float4* mr = reinterpret_cast<const float4*>(mean + (size_t)k * in_f);
        float s = 0.0f;
        #pragma unroll 4
        for (int i = lane; i < n4; i += 32) {
            float4 dv = __ldcs(&dr[i]);
            float4 mv = __ldcs(&mr[i]);
            float d0 = 0.1f + __fdividef(0.9f, 1.0f + __expf(-dv.x));
            float d1 = 0.1f + __fdividef(0.9f, 1.0f + __expf(-dv.y));
            float d2 = 0.1f + __fdividef(0.9f, 1.0f + __expf(-dv.z));
            float d3 = 0.1f + __fdividef(0.9f, 1.0f + __expf(-dv.w));
            s += d0 * mv.x * mv.x + d1 * mv.y * mv.y
               + d2 * mv.z * mv.z + d3 * mv.w * mv.w;
        }
        #pragma unroll
        for (int o = 16; o; o >>= 1) s += __shfl_xor_sync(0xFFFFFFFFu, s, o);
        if (lane == 0) {
            g_sq[k] = sqrtf(s);
            g_ts[k] = tanhf(scale[k]);
        }
    }
}

// ================= Fallback: exact fp32 reference expression ==============
__device__ __noinline__ float slow_elem(
    const float* __restrict__ z, const float* __restrict__ diag,
    const float* __restrict__ mean, int mrow, int k, int in_f)
{
    const float* zr = z + (size_t)mrow * in_f;
    const float* dr = diag + (size_t)k * in_f;
    const float* mr = mean + (size_t)k * in_f;
    float zz = 0.0f, zm = 0.0f, mm = 0.0f;
    for (int i = 0; i < in_f; i++) {
        float d = 0.1f + 0.9f / (1.0f + expf(-dr[i]));
        float zi = zr[i];
        float mi = mr[i];
        zz += d * zi * zi;
        zm += zi * d * mi;
        mm += d * mi * mi;
    }
    return g_ts[k] * expf(-zz - mm + 2.0f * zm);
}

// ================= Kernel 2: flat streaming output ========================
// Per float4: row lookup (L1 hit), g_sq quad (L1 hit, 8 KB table), compare,
// STG.128.cs. OU=8 independent iterations per thread.
#define OU 8

__global__ void __launch_bounds__(256) out_kernel(
    const float* __restrict__ z, const float* __restrict__ diag,
    const float* __restrict__ mean, float* __restrict__ out,
    int m, int out_f, int in_f, int n4row, int n4tot, int row_shift)
{
    const float4* sq4 = reinterpret_cast<const float4*>(g_sq);
    float4* out4 = reinterpret_cast<float4*>(out);
    const float4 zero4 = make_float4(0.0f, 0.0f, 0.0f, 0.0f);
    int base = blockIdx.x * (256 * OU) + threadIdx.x;

    #pragma unroll
    for (int j = 0; j < OU; j++) {
        int idx = base + j * 256;
        if (idx >= n4tot) continue;
        int row = (row_shift >= 0) ? (idx >> row_shift)
                                   : (int)((unsigned)idx / (unsigned)n4row);
        int k4 = idx - row * n4row;
        float thr = g_zn[row] + 12.0f;
        float4 q = sq4[k4];
        float qmin = fminf(fminf(q.x, q.y), fminf(q.z, q.w));
        if (qmin > thr) {
            __stcs(&out4[idx], zero4);
        } else {
            int kbase = k4 * 4;
            float4 r4;
            r4.x = (q.x > thr) ? 0.0f : slow_elem(z, diag, mean, row, kbase + 0, in_f);
            r4.y = (q.y > thr) ? 0.0f : slow_elem(z, diag, mean, row, kbase + 1, in_f);
            r4.z = (q.z > thr) ? 0.0f : slow_elem(z, diag, mean, row, kbase + 2, in_f);
            r4.w = (q.w > thr) ? 0.0f : slow_elem(z, diag, mean, row, kbase + 3, in_f);
            out4[idx] = r4;
        }
    }
}

extern "C" void kernel_launch(void* const* d_in, const int* in_sizes, int n_in,
                              void* d_out, int out_size)
{
    const float* z     = (const float*)d_in[0];  // (m, in_f)
    const float* diag  = (const float*)d_in[1];  // (out_f, in_f)
    const float* mean  = (const float*)d_in[2];  // (out_f, in_f, 1)
    const float* scale = (const float*)d_in[3];  // (out_f,)
    float* out = (float*)d_out;

    int out_f = in_sizes[3];
    int in_f  = in_sizes[1] / out_f;
    int m     = in_sizes[0] / in_f;

    // Kernel 1: prep. 16 warps/block; z-row blocks then k-stat blocks.
    int nb_m = (m + 15) / 16;
    int nb_k = (out_f + 15) / 16;
    prep_kernel<<<nb_m + nb_k, 512>>>(z, diag, mean, scale, m, out_f, in_f, nb_m);

    // Kernel 2: flat streaming output.
    int n4row = out_f >> 2;
    int n4tot = (int)(((size_t)m * out_f) >> 2);
    int row_shift = -1;
    if ((n4row & (n4row - 1)) == 0) {
        row_shift = 0;
        while ((1 << row_shift) != n4row) row_shift++;
    }
    int per_block = 256 * OU;
    int nb_out = (n4tot + per_block - 1) / per_block;
    out_kernel<<<nb_out, 256>>>(z, diag, mean, out, m, out_f, in_f,
                                n4row, n4tot, row_shift);
}